// round 1
// baseline (speedup 1.0000x reference)
#include <cuda_runtime.h>
#include <math.h>

#define BB 4
#define SSQ 2048
#define EE 2048
#define HH 8
#define OO 16
#define BSZ (BB*SSQ)      // 8192 rows
#define E4 (4*EE)         // 8192
#define MRU_SCALE 0.005f  // 0.08 / 16
#define LN_EPS 1e-5f

// ---------------- scratch (static device globals; no allocation allowed) ----
__device__ float g_x[(size_t)BSZ*EE];        // LN outputs (reused for ln1 and ln2)
__device__ float g_up[(size_t)BSZ*EE];       // per-token transition matrices (I + scale*up)
__device__ float g_down[(size_t)BSZ*EE];     // down-projected states
__device__ float g_hidden[(size_t)BSZ*E4];   // MLP hidden (gelu output)

// ---------------- LayerNorm (weight only, no bias) --------------------------
__global__ void ln_kernel(const float* __restrict__ in,
                          const float* __restrict__ gamma,
                          float* __restrict__ out)
{
    const int row = blockIdx.x;
    const float4* x4 = (const float4*)(in + (size_t)row * EE);
    float4* y4 = (float4*)(out + (size_t)row * EE);
    const float4* g4 = (const float4*)gamma;
    const int t = threadIdx.x;            // 256 threads, 8 elems each

    float4 a = x4[2*t], b = x4[2*t+1];
    float s  = a.x+a.y+a.z+a.w + b.x+b.y+b.z+b.w;
    float q  = a.x*a.x+a.y*a.y+a.z*a.z+a.w*a.w
             + b.x*b.x+b.y*b.y+b.z*b.z+b.w*b.w;
    #pragma unroll
    for (int o = 16; o > 0; o >>= 1) {
        s += __shfl_xor_sync(0xffffffffu, s, o);
        q += __shfl_xor_sync(0xffffffffu, q, o);
    }
    __shared__ float sm[8], sq[8];
    const int w = t >> 5, l = t & 31;
    if (l == 0) { sm[w] = s; sq[w] = q; }
    __syncthreads();
    if (w == 0) {
        s = sm[l & 7]; q = sq[l & 7];
        #pragma unroll
        for (int o = 4; o > 0; o >>= 1) {
            s += __shfl_xor_sync(0xffffffffu, s, o);
            q += __shfl_xor_sync(0xffffffffu, q, o);
        }
        if (l == 0) { sm[0] = s; sq[0] = q; }
    }
    __syncthreads();
    const float mean = sm[0] * (1.0f / EE);
    const float var  = sq[0] * (1.0f / EE) - mean * mean;
    const float r = rsqrtf(var + LN_EPS);

    float4 ga = g4[2*t], gb = g4[2*t+1];
    a.x = (a.x-mean)*r*ga.x; a.y = (a.y-mean)*r*ga.y;
    a.z = (a.z-mean)*r*ga.z; a.w = (a.w-mean)*r*ga.w;
    b.x = (b.x-mean)*r*gb.x; b.y = (b.y-mean)*r*gb.y;
    b.z = (b.z-mean)*r*gb.z; b.w = (b.w-mean)*r*gb.w;
    y4[2*t]   = a;
    y4[2*t+1] = b;
}

// ---------------- SGEMM: C = A[MxK] @ B[KxN] with fused epilogues -----------
// EPI: 0 = plain store
//      1 = v*SCALE + I (per 16x16 block inside each 256-wide head slot)
//      2 = v + Res[row,col]  (residual add; Res/C may alias elementwise)
//      3 = exact GELU
template<int EPI>
__global__ void __launch_bounds__(256, 2)
sgemm_kernel(int M, int N, int K,
             const float* __restrict__ A,
             const float* __restrict__ B,
             float* C,
             const float* Res)
{
    __shared__ float As[2][8][128];
    __shared__ float Bs[2][8][128];
    const int tid = threadIdx.x;
    const int bx = blockIdx.x, by = blockIdx.y;

    const int aRow = tid >> 1;
    const int aCol = (tid & 1) * 4;
    const int bRow = tid >> 5;
    const int bCol = (tid & 31) * 4;

    const float* Ap = A + (size_t)(by*128 + aRow) * K + aCol;
    const float* Bp = B + (size_t)bRow * N + (size_t)bx*128 + bCol;

    float acc[8][8];
    #pragma unroll
    for (int i = 0; i < 8; i++)
        #pragma unroll
        for (int j = 0; j < 8; j++) acc[i][j] = 0.f;

    {   // prologue: tile 0
        float4 av = *(const float4*)Ap;
        float4 bv = *(const float4*)Bp;
        As[0][aCol+0][aRow] = av.x; As[0][aCol+1][aRow] = av.y;
        As[0][aCol+2][aRow] = av.z; As[0][aCol+3][aRow] = av.w;
        *(float4*)&Bs[0][bRow][bCol] = bv;
    }
    __syncthreads();

    const int ty = (tid >> 4) * 8;
    const int tx = (tid & 15) * 8;
    const int ntiles = K >> 3;
    int cur = 0;

    for (int t = 0; t < ntiles; ++t) {
        float4 av, bv;
        const bool has_next = (t + 1 < ntiles);
        if (has_next) {
            Ap += 8;
            Bp += (size_t)8 * N;
            av = *(const float4*)Ap;
            bv = *(const float4*)Bp;
        }
        #pragma unroll
        for (int k = 0; k < 8; ++k) {
            float ra[8], rb[8];
            *(float4*)&ra[0] = *(const float4*)&As[cur][k][ty];
            *(float4*)&ra[4] = *(const float4*)&As[cur][k][ty+4];
            *(float4*)&rb[0] = *(const float4*)&Bs[cur][k][tx];
            *(float4*)&rb[4] = *(const float4*)&Bs[cur][k][tx+4];
            #pragma unroll
            for (int i = 0; i < 8; i++)
                #pragma unroll
                for (int j = 0; j < 8; j++)
                    acc[i][j] = fmaf(ra[i], rb[j], acc[i][j]);
        }
        if (has_next) {
            const int nxt = cur ^ 1;
            As[nxt][aCol+0][aRow] = av.x; As[nxt][aCol+1][aRow] = av.y;
            As[nxt][aCol+2][aRow] = av.z; As[nxt][aCol+3][aRow] = av.w;
            *(float4*)&Bs[nxt][bRow][bCol] = bv;
            __syncthreads();
            cur = nxt;
        }
    }

    const size_t row0 = (size_t)by*128 + ty;
    const int col0 = bx*128 + tx;
    #pragma unroll
    for (int i = 0; i < 8; i++) {
        const size_t off = (row0 + i) * N + col0;
        float v[8];
        #pragma unroll
        for (int j = 0; j < 8; j++) v[j] = acc[i][j];
        if (EPI == 1) {
            #pragma unroll
            for (int j = 0; j < 8; j++) {
                const int hc = (col0 + j) & 255;   // within one head's 16x16 block
                v[j] = v[j]*MRU_SCALE + (((hc >> 4) == (hc & 15)) ? 1.0f : 0.0f);
            }
        } else if (EPI == 2) {
            float4 r0 = *(const float4*)&Res[off];
            float4 r1 = *(const float4*)&Res[off+4];
            v[0]+=r0.x; v[1]+=r0.y; v[2]+=r0.z; v[3]+=r0.w;
            v[4]+=r1.x; v[5]+=r1.y; v[6]+=r1.z; v[7]+=r1.w;
        } else if (EPI == 3) {
            #pragma unroll
            for (int j = 0; j < 8; j++)
                v[j] = 0.5f * v[j] * (1.0f + erff(v[j] * 0.70710678118654752f));
        }
        *(float4*)&C[off]   = make_float4(v[0],v[1],v[2],v[3]);
        *(float4*)&C[off+4] = make_float4(v[4],v[5],v[6],v[7]);
    }
}

// ---------------- sequential matrix prefix-product scan ---------------------
// One block per (b,h) chain. state <- state @ M_s, left-to-right.
// Also fuses the down projection (state @ w_down[h]) and emits states for b=B-1.
__global__ void scan_kernel(const float* __restrict__ newm,      // [BSZ, EE]
                            const float* __restrict__ lstate,    // [B,H,O,O]
                            const float* __restrict__ wdn,       // [H,O,C]
                            float* __restrict__ dout,            // [BSZ, EE]
                            float* __restrict__ out_states,      // [S,H,O,O] (b=B-1)
                            int write_states)
{
    const int b = blockIdx.x >> 3;
    const int h = blockIdx.x & 7;
    const int t = threadIdx.x;            // 256 = one element of the 16x16 tile
    const int o = t >> 4, c = t & 15;

    __shared__ float st[2][256];
    __shared__ float Ms[256];
    __shared__ float wd[256];

    wd[t]   = wdn[h*256 + t];
    st[0][t] = lstate[(b*HH + h)*256 + t];

    const float* mp = newm + (size_t)(b*SSQ) * EE + h*256 + t;
    float* dp = dout + (size_t)(b*SSQ) * EE + h*256 + t;

    float mnext = mp[0];
    __syncthreads();

    int cur = 0;
    for (int s = 0; s < SSQ; ++s) {
        Ms[t] = mnext;
        if (s + 1 < SSQ) mnext = mp[(size_t)(s+1) * EE];   // prefetch next M
        __syncthreads();
        float acc = 0.f;
        #pragma unroll
        for (int q = 0; q < 16; q++)
            acc = fmaf(st[cur][o*16 + q], Ms[q*16 + c], acc);
        st[cur ^ 1][t] = acc;
        __syncthreads();
        cur ^= 1;
        float d = 0.f;
        #pragma unroll
        for (int q = 0; q < 16; q++)
            d = fmaf(st[cur][o*16 + q], wd[q*16 + c], d);
        dp[(size_t)s * EE] = d;
        if (write_states && b == BB-1)
            out_states[(size_t)s * EE + h*256 + t] = acc;
    }
}

// ---------------- launch ----------------------------------------------------
extern "C" void kernel_launch(void* const* d_in, const int* in_sizes, int n_in,
                              void* d_out, int out_size)
{
    const float* act    = (const float*)d_in[0];
    const float* lstate = (const float*)d_in[1];
    const float* w_up   = (const float*)d_in[2];
    const float* w_down = (const float*)d_in[3];
    const float* w_out  = (const float*)d_in[4];
    const float* ln1g   = (const float*)d_in[5];
    const float* ln2g   = (const float*)d_in[6];
    const float* w_mlp1 = (const float*)d_in[7];
    const float* w_mlp2 = (const float*)d_in[8];
    float* out = (float*)d_out;

    float *gx, *gup, *gdown, *ghid;
    cudaGetSymbolAddress((void**)&gx,    g_x);
    cudaGetSymbolAddress((void**)&gup,   g_up);
    cudaGetSymbolAddress((void**)&gdown, g_down);
    cudaGetSymbolAddress((void**)&ghid,  g_hidden);

    float* out_act = out;
    const long long need = (long long)BSZ*EE + (long long)SSQ*EE;
    const int write_states = ((long long)out_size >= need) ? 1 : 0;
    float* out_states = write_states ? (out + (size_t)BSZ*EE) : gx; // dummy target if absent

    // 1) x = LN(activations) * ln1_g
    ln_kernel<<<BSZ, 256>>>(act, ln1g, gx);

    // 2) new_m = (x @ w_up) * SCALE + I   (fused epilogue)
    {
        dim3 g(EE/128, BSZ/128);
        sgemm_kernel<1><<<g, 256>>>(BSZ, EE, EE, gx, w_up, gup, nullptr);
    }

    // 3) prefix matrix-product scan + down projection + states[-1] output
    scan_kernel<<<BB*HH, 256>>>(gup, lstate, w_down, gdown, out_states, write_states);

    // 4) act = activations + down @ w_out   -> d_out (act region)
    {
        dim3 g(EE/128, BSZ/128);
        sgemm_kernel<2><<<g, 256>>>(BSZ, EE, EE, gdown, w_out, out_act, act);
    }

    // 5) y = LN(act) * ln2_g
    ln_kernel<<<BSZ, 256>>>(out_act, ln2g, gx);

    // 6) hidden = gelu(y @ w_mlp1)
    {
        dim3 g(E4/128, BSZ/128);
        sgemm_kernel<3><<<g, 256>>>(BSZ, E4, EE, gx, w_mlp1, ghid, nullptr);
    }

    // 7) act = act + hidden @ w_mlp2   (in-place residual on d_out)
    {
        dim3 g(EE/128, BSZ/128);
        sgemm_kernel<2><<<g, 256>>>(BSZ, EE, E4, ghid, w_mlp2, out_act, out_act);
    }
}

// round 7
// speedup vs baseline: 1.9786x; 1.9786x over previous
#include <cuda_runtime.h>
#include <cuda_bf16.h>
#include <cstdint>
#include <math.h>

#define BB 4
#define SSQ 2048
#define EE 2048
#define HH 8
#define BSZ (BB*SSQ)          // 8192
#define MRU_SCALE 0.005f
#define LN_EPS 1e-5f

typedef __nv_bfloat16 bf16;

// ---------------------------------------------------------------------------
// PTX helpers — sm_80-era features only (plain sm_100 target safe)
// ---------------------------------------------------------------------------
__device__ __forceinline__ uint32_t smem_to_u32(const void* p) {
    uint32_t a;
    asm("{ .reg .u64 t; cvta.to.shared.u64 t, %1; cvt.u32.u64 %0, t; }" : "=r"(a) : "l"(p));
    return a;
}
__device__ __forceinline__ void cp_async16(uint32_t dst, const void* src) {
    asm volatile("cp.async.cg.shared.global [%0], [%1], 16;" :: "r"(dst), "l"(src) : "memory");
}
__device__ __forceinline__ void ldsm4(uint32_t* r, uint32_t addr) {
    asm volatile("ldmatrix.sync.aligned.m8n8.x4.shared.b16 {%0,%1,%2,%3}, [%4];"
        : "=r"(r[0]), "=r"(r[1]), "=r"(r[2]), "=r"(r[3]) : "r"(addr));
}
__device__ __forceinline__ void mma16816(float* d, const uint32_t* a, uint32_t b0, uint32_t b1) {
    asm volatile("mma.sync.aligned.m16n8k16.row.col.f32.bf16.bf16.f32 "
        "{%0,%1,%2,%3}, {%4,%5,%6,%7}, {%8,%9}, {%0,%1,%2,%3};"
        : "+f"(d[0]), "+f"(d[1]), "+f"(d[2]), "+f"(d[3])
        : "r"(a[0]), "r"(a[1]), "r"(a[2]), "r"(a[3]), "r"(b0), "r"(b1));
}

// ---------------------------------------------------------------------------
// Scratch (static device globals; total = 469.8 MB)
// ---------------------------------------------------------------------------
__device__ bf16 g_a2 [(size_t)BSZ * 2 * EE];        // A [hi|lo], pitch 2*EE (67.1 MB)
__device__ bf16 g_a2b[(size_t)BSZ * 2 * 4 * EE];    // gelu A [hi|lo], pitch 8*EE (268.4 MB)
                                                    //   head also hosts w_up/w_out splits pre-GEMM3
__device__ bf16 g_bm1 [(size_t)4*EE * 2 * EE];      // w_mlp1^T [hi|lo] (67.1 MB)
__device__ bf16 g_bm2 [(size_t)EE * 2 * 4 * EE];    // w_mlp2^T [hi|lo] (67.1 MB)

__device__ __forceinline__ uint32_t pack_bf2(float x, float y) {
    uint32_t lo = (uint32_t)__bfloat16_as_ushort(__float2bfloat16_rn(x));
    uint32_t hi = (uint32_t)__bfloat16_as_ushort(__float2bfloat16_rn(y));
    return lo | (hi << 16);
}

// ---------------------------------------------------------------------------
// LayerNorm -> split bf16 [hi | lo], pitch 2*EE
// ---------------------------------------------------------------------------
__global__ void ln_split_kernel(const float* __restrict__ in,
                                const float* __restrict__ gamma,
                                bf16* __restrict__ out)
{
    const int row = blockIdx.x;
    const float4* x4 = (const float4*)(in + (size_t)row * EE);
    const float4* g4 = (const float4*)gamma;
    const int t = threadIdx.x;           // 256 threads, 8 elems each

    float4 a = x4[2*t], b = x4[2*t+1];
    float s  = a.x+a.y+a.z+a.w + b.x+b.y+b.z+b.w;
    float q  = a.x*a.x+a.y*a.y+a.z*a.z+a.w*a.w
             + b.x*b.x+b.y*b.y+b.z*b.z+b.w*b.w;
    #pragma unroll
    for (int o = 16; o > 0; o >>= 1) {
        s += __shfl_xor_sync(0xffffffffu, s, o);
        q += __shfl_xor_sync(0xffffffffu, q, o);
    }
    __shared__ float sm[8], sq[8];
    const int w = t >> 5, l = t & 31;
    if (l == 0) { sm[w] = s; sq[w] = q; }
    __syncthreads();
    if (w == 0) {
        s = sm[l & 7]; q = sq[l & 7];
        #pragma unroll
        for (int o = 4; o > 0; o >>= 1) {
            s += __shfl_xor_sync(0xffffffffu, s, o);
            q += __shfl_xor_sync(0xffffffffu, q, o);
        }
        if (l == 0) { sm[0] = s; sq[0] = q; }
    }
    __syncthreads();
    const float mean = sm[0] * (1.0f / EE);
    const float var  = sq[0] * (1.0f / EE) - mean * mean;
    const float r = rsqrtf(var + LN_EPS);

    float4 ga = g4[2*t], gb = g4[2*t+1];
    float v[8];
    v[0]=(a.x-mean)*r*ga.x; v[1]=(a.y-mean)*r*ga.y; v[2]=(a.z-mean)*r*ga.z; v[3]=(a.w-mean)*r*ga.w;
    v[4]=(b.x-mean)*r*gb.x; v[5]=(b.y-mean)*r*gb.y; v[6]=(b.z-mean)*r*gb.z; v[7]=(b.w-mean)*r*gb.w;

    float h[8], lo[8];
    #pragma unroll
    for (int j = 0; j < 8; j++) {
        h[j]  = __bfloat162float(__float2bfloat16_rn(v[j]));
        lo[j] = v[j] - h[j];
    }
    uint4 uh = make_uint4(pack_bf2(h[0],h[1]), pack_bf2(h[2],h[3]), pack_bf2(h[4],h[5]), pack_bf2(h[6],h[7]));
    uint4 ul = make_uint4(pack_bf2(lo[0],lo[1]), pack_bf2(lo[2],lo[3]), pack_bf2(lo[4],lo[5]), pack_bf2(lo[6],lo[7]));
    bf16* base = out + (size_t)row * (2*EE) + t*8;
    *(uint4*)(base)      = uh;
    *(uint4*)(base + EE) = ul;
}

// ---------------------------------------------------------------------------
// Transpose + split convert for weights: W[K,N] fp32 -> out[N, 2K] = [hi|lo]
// ---------------------------------------------------------------------------
__global__ void tconv_kernel(const float* __restrict__ W,
                             bf16* __restrict__ out, int K, int N)
{
    __shared__ float s[32][33];
    const int n0 = blockIdx.x * 32, k0 = blockIdx.y * 32;
    const int tx = threadIdx.x, ty = threadIdx.y;
    #pragma unroll
    for (int i = 0; i < 4; i++) {
        int k = k0 + ty + i*8;
        s[ty + i*8][tx] = W[(size_t)k * N + n0 + tx];
    }
    __syncthreads();
    const size_t p2k = 2 * (size_t)K;
    #pragma unroll
    for (int i = 0; i < 4; i++) {
        int n = n0 + ty + i*8;
        float v = s[tx][ty + i*8];
        bf16 h = __float2bfloat16_rn(v);
        bf16 l = __float2bfloat16_rn(v - __bfloat162float(h));
        size_t rb = (size_t)n * p2k + k0 + tx;
        out[rb]     = h;
        out[rb + K] = l;
    }
}

// ---------------------------------------------------------------------------
// mma.sync bf16 GEMM:  C[M,N] = sum over logical K' = 3*logK of A'[M,K'] B'[N,K']^T
// A' chunks map [hi|lo|hi], B' chunks map [hi|hi|lo] into packed [hi|lo]
// storage (pitch 2*logK):  a_off = kk<2K?kk:kk-2K ; b_off = kk<K?kk:kk-K.
// CTA tile 128x128, warp tile 64x32 (2x4 warps), K-chunk 32, double buffer.
// EPI: 1 = v*SCALE + I ; 2 = v + Res ; 3 = gelu -> split [hi|lo] pitch 2*k2out
// ---------------------------------------------------------------------------
#define PITCH 40            // bf16 per smem row (32 data + 8 pad) = 80B
#define PITCHB 80

template<int EPI>
__global__ void __launch_bounds__(256, 2)
mgemm_kernel(const bf16* __restrict__ A,
             const bf16* __restrict__ Bt,
             float* C, int ldc, int logK,
             const float* Res,
             bf16* split_out, int k2out)
{
    __shared__ bf16 sA[2][128*PITCH];
    __shared__ bf16 sB[2][128*PITCH];

    const int tid = threadIdx.x, wid = tid >> 5, lane = tid & 31;
    const int warp_m = wid & 1, warp_n = wid >> 1;
    const int m0 = blockIdx.y * 128, n0 = blockIdx.x * 128;
    const int lda = 2*logK, ldb = 2*logK;
    const int nchunk = (3*logK) >> 5;

    const uint32_t sAu = smem_to_u32(sA);
    const uint32_t sBu = smem_to_u32(sB);

    float acc[4][4][4];
    #pragma unroll
    for (int i = 0; i < 4; i++)
        #pragma unroll
        for (int j = 0; j < 4; j++)
            #pragma unroll
            for (int c = 0; c < 4; c++) acc[i][j][c] = 0.f;

    // load mapping: 512 16B-chunks per matrix per K-chunk; thread does 2 each
    const int lrow0 = tid >> 2;            // rows tid/4 and tid/4+64
    const int lc4   = tid & 3;             // 16B chunk within 64B row

    const bf16* aP = A  + (size_t)(m0 + lrow0) * lda + lc4*8;
    const bf16* bP = Bt + (size_t)(n0 + lrow0) * ldb + lc4*8;
    const size_t aStep64 = (size_t)64 * lda;
    const size_t bStep64 = (size_t)64 * ldb;
    const uint32_t sOff0 = (uint32_t)(lrow0*PITCHB + lc4*16);
    const uint32_t sOff1 = (uint32_t)((lrow0+64)*PITCHB + lc4*16);

    // ldmatrix base addressing: lane L -> row L%16, 16B chunk L/16
    const int lr = lane & 15, lc = lane >> 4;
    const uint32_t aBase = (uint32_t)((warp_m*64 + lr)*PITCHB + lc*16);
    const uint32_t bBase = (uint32_t)((warp_n*32 + lr)*PITCHB + lc*16);

    // prologue: chunk 0 into buf 0 (kk=0 -> aoff=boff=0)
    {
        cp_async16(sAu + sOff0, aP);
        cp_async16(sAu + sOff1, aP + aStep64);
        cp_async16(sBu + sOff0, bP);
        cp_async16(sBu + sOff1, bP + bStep64);
        asm volatile("cp.async.commit_group;" ::: "memory");
    }

    for (int c = 0; c < nchunk; c++) {
        if (c + 1 < nchunk) {
            const uint32_t bufo = ((c+1) & 1) ? (uint32_t)(128*PITCHB) : 0u;
            const int kk = (c+1) * 32;
            const int aoff = (kk < 2*logK) ? kk : kk - 2*logK;
            const int boff = (kk < logK)   ? kk : kk - logK;
            const bf16* ap = aP + aoff;
            const bf16* bp = bP + boff;
            cp_async16(sAu + bufo + sOff0, ap);
            cp_async16(sAu + bufo + sOff1, ap + aStep64);
            cp_async16(sBu + bufo + sOff0, bp);
            cp_async16(sBu + bufo + sOff1, bp + bStep64);
            asm volatile("cp.async.commit_group;" ::: "memory");
            asm volatile("cp.async.wait_group 1;" ::: "memory");
        } else {
            asm volatile("cp.async.wait_group 0;" ::: "memory");
        }
        __syncthreads();

        const uint32_t buf = (c & 1) ? (uint32_t)(128*PITCHB) : 0u;
        #pragma unroll
        for (int k16 = 0; k16 < 2; k16++) {
            const uint32_t ko = k16*32;
            uint32_t af[4][4], bfr[2][4];
            #pragma unroll
            for (int mi = 0; mi < 4; mi++)
                ldsm4(af[mi], sAu + buf + aBase + mi*16*PITCHB + ko);
            #pragma unroll
            for (int g = 0; g < 2; g++)
                ldsm4(bfr[g], sBu + buf + bBase + g*16*PITCHB + ko);
            #pragma unroll
            for (int mi = 0; mi < 4; mi++)
                #pragma unroll
                for (int ni = 0; ni < 4; ni++)
                    mma16816(acc[mi][ni], af[mi], bfr[ni>>1][ni&1], bfr[ni>>1][(ni&1)+2]);
        }
        __syncthreads();
    }

    // ---------------- epilogue --------------------------------------------
    const int erow = lane >> 2;           // 0..7
    const int ecol = (lane & 3) * 2;
    #pragma unroll
    for (int mi = 0; mi < 4; mi++) {
        #pragma unroll
        for (int ni = 0; ni < 4; ni++) {
            const int col = n0 + warp_n*32 + ni*8 + ecol;
            #pragma unroll
            for (int half = 0; half < 2; half++) {
                const int row = m0 + warp_m*64 + mi*16 + erow + half*8;
                float v0 = acc[mi][ni][half*2+0];
                float v1 = acc[mi][ni][half*2+1];
                if (EPI == 1) {
                    int h0 = col & 255, h1 = (col+1) & 255;
                    v0 = v0*MRU_SCALE + (((h0 >> 4) == (h0 & 15)) ? 1.0f : 0.0f);
                    v1 = v1*MRU_SCALE + (((h1 >> 4) == (h1 & 15)) ? 1.0f : 0.0f);
                    *(float2*)&C[(size_t)row * ldc + col] = make_float2(v0, v1);
                } else if (EPI == 2) {
                    float2 r = *(const float2*)&Res[(size_t)row * ldc + col];
                    *(float2*)&C[(size_t)row * ldc + col] = make_float2(v0 + r.x, v1 + r.y);
                } else {
                    float g0 = 0.5f * v0 * (1.0f + erff(v0 * 0.70710678118654752f));
                    float g1 = 0.5f * v1 * (1.0f + erff(v1 * 0.70710678118654752f));
                    float h0 = __bfloat162float(__float2bfloat16_rn(g0));
                    float h1 = __bfloat162float(__float2bfloat16_rn(g1));
                    uint32_t uh = pack_bf2(h0, h1);
                    uint32_t ul = pack_bf2(g0 - h0, g1 - h1);
                    size_t rb = (size_t)row * (size_t)(2*k2out) + col;
                    *(uint32_t*)&split_out[rb]         = uh;
                    *(uint32_t*)&split_out[rb + k2out] = ul;
                }
            }
        }
    }
}

// ---------------------------------------------------------------------------
// Sequential matrix prefix-product scan; emits A-side split [hi|lo] pitch 2*EE
// ---------------------------------------------------------------------------
__global__ void scan_kernel(const float* __restrict__ newm,      // [BSZ, EE]
                            const float* __restrict__ lstate,    // [B,H,O,O]
                            const float* __restrict__ wdn,       // [H,O,C]
                            bf16* __restrict__ dsplit,           // [BSZ, 2*EE]
                            float* __restrict__ out_states,
                            int write_states)
{
    const int b = blockIdx.x >> 3;
    const int h = blockIdx.x & 7;
    const int t = threadIdx.x;            // 256 = one element of the 16x16 tile
    const int o = t >> 4, c = t & 15;

    __shared__ float st[2][256];
    __shared__ float Ms[256];
    __shared__ float wd[256];

    wd[t]    = wdn[h*256 + t];
    st[0][t] = lstate[(b*HH + h)*256 + t];

    const float* mp = newm + (size_t)(b*SSQ) * EE + h*256 + t;
    bf16* dp = dsplit + (size_t)(b*SSQ) * (2*EE) + h*256 + t;

    float mnext = mp[0];
    __syncthreads();

    int cur = 0;
    for (int s = 0; s < SSQ; ++s) {
        Ms[t] = mnext;
        if (s + 1 < SSQ) mnext = mp[(size_t)(s+1) * EE];
        __syncthreads();
        float acc = 0.f;
        #pragma unroll
        for (int q = 0; q < 16; q++)
            acc = fmaf(st[cur][o*16 + q], Ms[q*16 + c], acc);
        st[cur ^ 1][t] = acc;
        __syncthreads();
        cur ^= 1;
        float d = 0.f;
        #pragma unroll
        for (int q = 0; q < 16; q++)
            d = fmaf(st[cur][o*16 + q], wd[q*16 + c], d);
        bf16 hB = __float2bfloat16_rn(d);
        bf16 lB = __float2bfloat16_rn(d - __bfloat162float(hB));
        bf16* drow = dp + (size_t)s * (2*EE);
        drow[0]  = hB;
        drow[EE] = lB;
        if (write_states && b == BB-1)
            out_states[(size_t)s * EE + h*256 + t] = acc;
    }
}

// ---------------------------------------------------------------------------
// launch
// ---------------------------------------------------------------------------
extern "C" void kernel_launch(void* const* d_in, const int* in_sizes, int n_in,
                              void* d_out, int out_size)
{
    const float* act    = (const float*)d_in[0];
    const float* lstate = (const float*)d_in[1];
    const float* w_up   = (const float*)d_in[2];
    const float* w_down = (const float*)d_in[3];
    const float* w_out  = (const float*)d_in[4];
    const float* ln1g   = (const float*)d_in[5];
    const float* ln2g   = (const float*)d_in[6];
    const float* w_mlp1 = (const float*)d_in[7];
    const float* w_mlp2 = (const float*)d_in[8];
    float* out = (float*)d_out;

    bf16 *ga2, *ga2b, *gbm1, *gbm2;
    cudaGetSymbolAddress((void**)&ga2,  g_a2);
    cudaGetSymbolAddress((void**)&ga2b, g_a2b);
    cudaGetSymbolAddress((void**)&gbm1, g_bm1);
    cudaGetSymbolAddress((void**)&gbm2, g_bm2);

    // w_up / w_out splits live in the head of g_a2b (dead until GEMM3 epilogue)
    bf16* gbup  = ga2b;                                   // [EE, 2*EE] = 16.8 MB
    bf16* gbout = ga2b + (size_t)EE * 2 * EE;             // next 16.8 MB

    float* out_act = out;
    const long long need = (long long)BSZ*EE + (long long)SSQ*EE;
    const int write_states = ((long long)out_size >= need) ? 1 : 0;
    // fallback scratch for states (region of g_a2b past the weight splits;
    // overwritten later by GEMM3 epilogue, scan runs before GEMM3)
    float* out_states = write_states ? (out + (size_t)BSZ*EE)
                                     : (float*)(ga2b + (size_t)4 * EE * 2 * EE);

    // weight transpose+split conversions (independent; issue first)
    tconv_kernel<<<dim3(EE/32,   EE/32),   dim3(32,8)>>>(w_up,   gbup, EE,   EE);
    tconv_kernel<<<dim3(EE/32,   EE/32),   dim3(32,8)>>>(w_out,  gbout,EE,   EE);
    tconv_kernel<<<dim3(4*EE/32, EE/32),   dim3(32,8)>>>(w_mlp1, gbm1, EE,   4*EE);
    tconv_kernel<<<dim3(EE/32,   4*EE/32), dim3(32,8)>>>(w_mlp2, gbm2, 4*EE, EE);

    // 1) ln1 -> A split
    ln_split_kernel<<<BSZ, 256>>>(act, ln1g, ga2);

    // 2) new_m = (x @ w_up) * SCALE + I   -> stored in d_out act region (fp32)
    mgemm_kernel<1><<<dim3(EE/128, BSZ/128), 256>>>(
        ga2, gbup, out_act, EE, EE, nullptr, nullptr, 0);

    // 3) scan (reads newm from d_out) -> A split for gemm2 + states output
    scan_kernel<<<BB*HH, 256>>>(out_act, lstate, w_down, ga2, out_states, write_states);

    // 4) act = activations + down @ w_out  (overwrites consumed newm in d_out)
    mgemm_kernel<2><<<dim3(EE/128, BSZ/128), 256>>>(
        ga2, gbout, out_act, EE, EE, act, nullptr, 0);

    // 5) ln2 -> A split
    ln_split_kernel<<<BSZ, 256>>>(out_act, ln2g, ga2);

    // 6) hidden = gelu(y @ w_mlp1) -> A split for gemm4 (overwrites g_a2b incl. dead w_up/w_out)
    mgemm_kernel<3><<<dim3(4*EE/128, BSZ/128), 256>>>(
        ga2, gbm1, nullptr, 4*EE, EE, nullptr, ga2b, 4*EE);

    // 7) act = act + hidden @ w_mlp2  (in-place residual on d_out)
    mgemm_kernel<2><<<dim3(EE/128, BSZ/128), 256>>>(
        ga2b, gbm2, out_act, EE, 4*EE, out_act, nullptr, 0);
}

// round 8
// speedup vs baseline: 1.9827x; 1.0021x over previous
#include <cuda_runtime.h>
#include <cuda_bf16.h>
#include <cstdint>
#include <math.h>

#define BB 4
#define SSQ 2048
#define EE 2048
#define HH 8
#define BSZ (BB*SSQ)          // 8192
#define MRU_SCALE 0.005f
#define LN_EPS 1e-5f

typedef __nv_bfloat16 bf16;

// ---------------------------------------------------------------------------
// PTX helpers — sm_80-era features only (plain sm_100 target safe)
// ---------------------------------------------------------------------------
__device__ __forceinline__ uint32_t smem_to_u32(const void* p) {
    uint32_t a;
    asm("{ .reg .u64 t; cvta.to.shared.u64 t, %1; cvt.u32.u64 %0, t; }" : "=r"(a) : "l"(p));
    return a;
}
__device__ __forceinline__ void cp_async16(uint32_t dst, const void* src) {
    asm volatile("cp.async.cg.shared.global [%0], [%1], 16;" :: "r"(dst), "l"(src) : "memory");
}
__device__ __forceinline__ void ldsm4(uint32_t* r, uint32_t addr) {
    asm volatile("ldmatrix.sync.aligned.m8n8.x4.shared.b16 {%0,%1,%2,%3}, [%4];"
        : "=r"(r[0]), "=r"(r[1]), "=r"(r[2]), "=r"(r[3]) : "r"(addr));
}
__device__ __forceinline__ void mma16816(float* d, const uint32_t* a, uint32_t b0, uint32_t b1) {
    asm volatile("mma.sync.aligned.m16n8k16.row.col.f32.bf16.bf16.f32 "
        "{%0,%1,%2,%3}, {%4,%5,%6,%7}, {%8,%9}, {%0,%1,%2,%3};"
        : "+f"(d[0]), "+f"(d[1]), "+f"(d[2]), "+f"(d[3])
        : "r"(a[0]), "r"(a[1]), "r"(a[2]), "r"(a[3]), "r"(b0), "r"(b1));
}

// ---------------------------------------------------------------------------
// Scratch (static device globals; total = 469.8 MB)
// ---------------------------------------------------------------------------
__device__ bf16 g_a2 [(size_t)BSZ * 2 * EE];        // A [hi|lo], pitch 2*EE (67.1 MB)
__device__ bf16 g_a2b[(size_t)BSZ * 2 * 4 * EE];    // gelu A [hi|lo], pitch 8*EE (268.4 MB)
                                                    //   head also hosts w_up/w_out splits pre-GEMM3
__device__ bf16 g_bm1 [(size_t)4*EE * 2 * EE];      // w_mlp1^T [hi|lo] (67.1 MB)
__device__ bf16 g_bm2 [(size_t)EE * 2 * 4 * EE];    // w_mlp2^T [hi|lo] (67.1 MB)

__device__ __forceinline__ uint32_t pack_bf2(float x, float y) {
    uint32_t lo = (uint32_t)__bfloat16_as_ushort(__float2bfloat16_rn(x));
    uint32_t hi = (uint32_t)__bfloat16_as_ushort(__float2bfloat16_rn(y));
    return lo | (hi << 16);
}

// ---------------------------------------------------------------------------
// LayerNorm -> split bf16 [hi | lo], pitch 2*EE
// ---------------------------------------------------------------------------
__global__ void ln_split_kernel(const float* __restrict__ in,
                                const float* __restrict__ gamma,
                                bf16* __restrict__ out)
{
    const int row = blockIdx.x;
    const float4* x4 = (const float4*)(in + (size_t)row * EE);
    const float4* g4 = (const float4*)gamma;
    const int t = threadIdx.x;           // 256 threads, 8 elems each

    float4 a = x4[2*t], b = x4[2*t+1];
    float s  = a.x+a.y+a.z+a.w + b.x+b.y+b.z+b.w;
    float q  = a.x*a.x+a.y*a.y+a.z*a.z+a.w*a.w
             + b.x*b.x+b.y*b.y+b.z*b.z+b.w*b.w;
    #pragma unroll
    for (int o = 16; o > 0; o >>= 1) {
        s += __shfl_xor_sync(0xffffffffu, s, o);
        q += __shfl_xor_sync(0xffffffffu, q, o);
    }
    __shared__ float sm[8], sq[8];
    const int w = t >> 5, l = t & 31;
    if (l == 0) { sm[w] = s; sq[w] = q; }
    __syncthreads();
    if (w == 0) {
        s = sm[l & 7]; q = sq[l & 7];
        #pragma unroll
        for (int o = 4; o > 0; o >>= 1) {
            s += __shfl_xor_sync(0xffffffffu, s, o);
            q += __shfl_xor_sync(0xffffffffu, q, o);
        }
        if (l == 0) { sm[0] = s; sq[0] = q; }
    }
    __syncthreads();
    const float mean = sm[0] * (1.0f / EE);
    const float var  = sq[0] * (1.0f / EE) - mean * mean;
    const float r = rsqrtf(var + LN_EPS);

    float4 ga = g4[2*t], gb = g4[2*t+1];
    float v[8];
    v[0]=(a.x-mean)*r*ga.x; v[1]=(a.y-mean)*r*ga.y; v[2]=(a.z-mean)*r*ga.z; v[3]=(a.w-mean)*r*ga.w;
    v[4]=(b.x-mean)*r*gb.x; v[5]=(b.y-mean)*r*gb.y; v[6]=(b.z-mean)*r*gb.z; v[7]=(b.w-mean)*r*gb.w;

    float h[8], lo[8];
    #pragma unroll
    for (int j = 0; j < 8; j++) {
        h[j]  = __bfloat162float(__float2bfloat16_rn(v[j]));
        lo[j] = v[j] - h[j];
    }
    uint4 uh = make_uint4(pack_bf2(h[0],h[1]), pack_bf2(h[2],h[3]), pack_bf2(h[4],h[5]), pack_bf2(h[6],h[7]));
    uint4 ul = make_uint4(pack_bf2(lo[0],lo[1]), pack_bf2(lo[2],lo[3]), pack_bf2(lo[4],lo[5]), pack_bf2(lo[6],lo[7]));
    bf16* base = out + (size_t)row * (2*EE) + t*8;
    *(uint4*)(base)      = uh;
    *(uint4*)(base + EE) = ul;
}

// ---------------------------------------------------------------------------
// Transpose + split convert for weights: W[K,N] fp32 -> out[N, 2K] = [hi|lo]
// ---------------------------------------------------------------------------
__global__ void tconv_kernel(const float* __restrict__ W,
                             bf16* __restrict__ out, int K, int N)
{
    __shared__ float s[32][33];
    const int n0 = blockIdx.x * 32, k0 = blockIdx.y * 32;
    const int tx = threadIdx.x, ty = threadIdx.y;
    #pragma unroll
    for (int i = 0; i < 4; i++) {
        int k = k0 + ty + i*8;
        s[ty + i*8][tx] = W[(size_t)k * N + n0 + tx];
    }
    __syncthreads();
    const size_t p2k = 2 * (size_t)K;
    #pragma unroll
    for (int i = 0; i < 4; i++) {
        int n = n0 + ty + i*8;
        float v = s[tx][ty + i*8];
        bf16 h = __float2bfloat16_rn(v);
        bf16 l = __float2bfloat16_rn(v - __bfloat162float(h));
        size_t rb = (size_t)n * p2k + k0 + tx;
        out[rb]     = h;
        out[rb + K] = l;
    }
}

// ---------------------------------------------------------------------------
// mma.sync bf16 GEMM:  C[M,N] = sum over logical K' = 3*logK of A'[M,K'] B'[N,K']^T
// A' chunks map [hi|lo|hi], B' chunks map [hi|hi|lo] into packed [hi|lo]
// storage (pitch 2*logK):  a_off = kk<2K?kk:kk-2K ; b_off = kk<K?kk:kk-K.
// CTA tile 128x128, warp tile 64x32 (2x4 warps), K-chunk 32, double buffer.
// EPI: 1 = v*SCALE + I ; 2 = v + Res ; 3 = gelu -> split [hi|lo] pitch 2*k2out
// ---------------------------------------------------------------------------
#define PITCH 40            // bf16 per smem row (32 data + 8 pad) = 80B
#define PITCHB 80

template<int EPI>
__global__ void __launch_bounds__(256, 2)
mgemm_kernel(const bf16* __restrict__ A,
             const bf16* __restrict__ Bt,
             float* C, int ldc, int logK,
             const float* Res,
             bf16* split_out, int k2out)
{
    __shared__ bf16 sA[2][128*PITCH];
    __shared__ bf16 sB[2][128*PITCH];

    const int tid = threadIdx.x, wid = tid >> 5, lane = tid & 31;
    const int warp_m = wid & 1, warp_n = wid >> 1;
    const int m0 = blockIdx.y * 128, n0 = blockIdx.x * 128;
    const int lda = 2*logK, ldb = 2*logK;
    const int nchunk = (3*logK) >> 5;

    const uint32_t sAu = smem_to_u32(sA);
    const uint32_t sBu = smem_to_u32(sB);

    float acc[4][4][4];
    #pragma unroll
    for (int i = 0; i < 4; i++)
        #pragma unroll
        for (int j = 0; j < 4; j++)
            #pragma unroll
            for (int c = 0; c < 4; c++) acc[i][j][c] = 0.f;

    // load mapping: 512 16B-chunks per matrix per K-chunk; thread does 2 each
    const int lrow0 = tid >> 2;            // rows tid/4 and tid/4+64
    const int lc4   = tid & 3;             // 16B chunk within 64B row

    const bf16* aP = A  + (size_t)(m0 + lrow0) * lda + lc4*8;
    const bf16* bP = Bt + (size_t)(n0 + lrow0) * ldb + lc4*8;
    const size_t aStep64 = (size_t)64 * lda;
    const size_t bStep64 = (size_t)64 * ldb;
    const uint32_t sOff0 = (uint32_t)(lrow0*PITCHB + lc4*16);
    const uint32_t sOff1 = (uint32_t)((lrow0+64)*PITCHB + lc4*16);

    // ldmatrix base addressing: lane L -> row L%16, 16B chunk L/16
    const int lr = lane & 15, lc = lane >> 4;
    const uint32_t aBase = (uint32_t)((warp_m*64 + lr)*PITCHB + lc*16);
    const uint32_t bBase = (uint32_t)((warp_n*32 + lr)*PITCHB + lc*16);

    // prologue: chunk 0 into buf 0 (kk=0 -> aoff=boff=0)
    {
        cp_async16(sAu + sOff0, aP);
        cp_async16(sAu + sOff1, aP + aStep64);
        cp_async16(sBu + sOff0, bP);
        cp_async16(sBu + sOff1, bP + bStep64);
        asm volatile("cp.async.commit_group;" ::: "memory");
    }

    for (int c = 0; c < nchunk; c++) {
        if (c + 1 < nchunk) {
            const uint32_t bufo = ((c+1) & 1) ? (uint32_t)(128*PITCHB) : 0u;
            const int kk = (c+1) * 32;
            const int aoff = (kk < 2*logK) ? kk : kk - 2*logK;
            const int boff = (kk < logK)   ? kk : kk - logK;
            const bf16* ap = aP + aoff;
            const bf16* bp = bP + boff;
            cp_async16(sAu + bufo + sOff0, ap);
            cp_async16(sAu + bufo + sOff1, ap + aStep64);
            cp_async16(sBu + bufo + sOff0, bp);
            cp_async16(sBu + bufo + sOff1, bp + bStep64);
            asm volatile("cp.async.commit_group;" ::: "memory");
            asm volatile("cp.async.wait_group 1;" ::: "memory");
        } else {
            asm volatile("cp.async.wait_group 0;" ::: "memory");
        }
        __syncthreads();

        const uint32_t buf = (c & 1) ? (uint32_t)(128*PITCHB) : 0u;
        #pragma unroll
        for (int k16 = 0; k16 < 2; k16++) {
            const uint32_t ko = k16*32;
            uint32_t af[4][4], bfr[2][4];
            #pragma unroll
            for (int mi = 0; mi < 4; mi++)
                ldsm4(af[mi], sAu + buf + aBase + mi*16*PITCHB + ko);
            #pragma unroll
            for (int g = 0; g < 2; g++)
                ldsm4(bfr[g], sBu + buf + bBase + g*16*PITCHB + ko);
            #pragma unroll
            for (int mi = 0; mi < 4; mi++)
                #pragma unroll
                for (int ni = 0; ni < 4; ni++)
                    mma16816(acc[mi][ni], af[mi], bfr[ni>>1][ni&1], bfr[ni>>1][(ni&1)+2]);
        }
        __syncthreads();
    }

    // ---------------- epilogue --------------------------------------------
    const int erow = lane >> 2;           // 0..7
    const int ecol = (lane & 3) * 2;
    #pragma unroll
    for (int mi = 0; mi < 4; mi++) {
        #pragma unroll
        for (int ni = 0; ni < 4; ni++) {
            const int col = n0 + warp_n*32 + ni*8 + ecol;
            #pragma unroll
            for (int half = 0; half < 2; half++) {
                const int row = m0 + warp_m*64 + mi*16 + erow + half*8;
                float v0 = acc[mi][ni][half*2+0];
                float v1 = acc[mi][ni][half*2+1];
                if (EPI == 1) {
                    int h0 = col & 255, h1 = (col+1) & 255;
                    v0 = v0*MRU_SCALE + (((h0 >> 4) == (h0 & 15)) ? 1.0f : 0.0f);
                    v1 = v1*MRU_SCALE + (((h1 >> 4) == (h1 & 15)) ? 1.0f : 0.0f);
                    *(float2*)&C[(size_t)row * ldc + col] = make_float2(v0, v1);
                } else if (EPI == 2) {
                    float2 r = *(const float2*)&Res[(size_t)row * ldc + col];
                    *(float2*)&C[(size_t)row * ldc + col] = make_float2(v0 + r.x, v1 + r.y);
                } else {
                    float g0 = 0.5f * v0 * (1.0f + erff(v0 * 0.70710678118654752f));
                    float g1 = 0.5f * v1 * (1.0f + erff(v1 * 0.70710678118654752f));
                    float h0 = __bfloat162float(__float2bfloat16_rn(g0));
                    float h1 = __bfloat162float(__float2bfloat16_rn(g1));
                    uint32_t uh = pack_bf2(h0, h1);
                    uint32_t ul = pack_bf2(g0 - h0, g1 - h1);
                    size_t rb = (size_t)row * (size_t)(2*k2out) + col;
                    *(uint32_t*)&split_out[rb]         = uh;
                    *(uint32_t*)&split_out[rb + k2out] = ul;
                }
            }
        }
    }
}

// ---------------------------------------------------------------------------
// Sequential matrix prefix-product scan; emits A-side split [hi|lo] pitch 2*EE
// ---------------------------------------------------------------------------
__global__ void scan_kernel(const float* __restrict__ newm,      // [BSZ, EE]
                            const float* __restrict__ lstate,    // [B,H,O,O]
                            const float* __restrict__ wdn,       // [H,O,C]
                            bf16* __restrict__ dsplit,           // [BSZ, 2*EE]
                            float* __restrict__ out_states,
                            int write_states)
{
    const int b = blockIdx.x >> 3;
    const int h = blockIdx.x & 7;
    const int t = threadIdx.x;            // 256 = one element of the 16x16 tile
    const int o = t >> 4, c = t & 15;

    __shared__ float st[2][256];
    __shared__ float Ms[256];
    __shared__ float wd[256];

    wd[t]    = wdn[h*256 + t];
    st[0][t] = lstate[(b*HH + h)*256 + t];

    const float* mp = newm + (size_t)(b*SSQ) * EE + h*256 + t;
    bf16* dp = dsplit + (size_t)(b*SSQ) * (2*EE) + h*256 + t;

    float mnext = mp[0];
    __syncthreads();

    int cur = 0;
    for (int s = 0; s < SSQ; ++s) {
        Ms[t] = mnext;
        if (s + 1 < SSQ) mnext = mp[(size_t)(s+1) * EE];
        __syncthreads();
        float acc = 0.f;
        #pragma unroll
        for (int q = 0; q < 16; q++)
            acc = fmaf(st[cur][o*16 + q], Ms[q*16 + c], acc);
        st[cur ^ 1][t] = acc;
        __syncthreads();
        cur ^= 1;
        float d = 0.f;
        #pragma unroll
        for (int q = 0; q < 16; q++)
            d = fmaf(st[cur][o*16 + q], wd[q*16 + c], d);
        bf16 hB = __float2bfloat16_rn(d);
        bf16 lB = __float2bfloat16_rn(d - __bfloat162float(hB));
        bf16* drow = dp + (size_t)s * (2*EE);
        drow[0]  = hB;
        drow[EE] = lB;
        if (write_states && b == BB-1)
            out_states[(size_t)s * EE + h*256 + t] = acc;
    }
}

// ---------------------------------------------------------------------------
// launch
// ---------------------------------------------------------------------------
extern "C" void kernel_launch(void* const* d_in, const int* in_sizes, int n_in,
                              void* d_out, int out_size)
{
    const float* act    = (const float*)d_in[0];
    const float* lstate = (const float*)d_in[1];
    const float* w_up   = (const float*)d_in[2];
    const float* w_down = (const float*)d_in[3];
    const float* w_out  = (const float*)d_in[4];
    const float* ln1g   = (const float*)d_in[5];
    const float* ln2g   = (const float*)d_in[6];
    const float* w_mlp1 = (const float*)d_in[7];
    const float* w_mlp2 = (const float*)d_in[8];
    float* out = (float*)d_out;

    bf16 *ga2, *ga2b, *gbm1, *gbm2;
    cudaGetSymbolAddress((void**)&ga2,  g_a2);
    cudaGetSymbolAddress((void**)&ga2b, g_a2b);
    cudaGetSymbolAddress((void**)&gbm1, g_bm1);
    cudaGetSymbolAddress((void**)&gbm2, g_bm2);

    // w_up / w_out splits live in the head of g_a2b (dead until GEMM3 epilogue)
    bf16* gbup  = ga2b;                                   // [EE, 2*EE] = 16.8 MB
    bf16* gbout = ga2b + (size_t)EE * 2 * EE;             // next 16.8 MB

    float* out_act = out;
    const long long need = (long long)BSZ*EE + (long long)SSQ*EE;
    const int write_states = ((long long)out_size >= need) ? 1 : 0;
    // fallback scratch for states (region of g_a2b past the weight splits;
    // overwritten later by GEMM3 epilogue, scan runs before GEMM3)
    float* out_states = write_states ? (out + (size_t)BSZ*EE)
                                     : (float*)(ga2b + (size_t)4 * EE * 2 * EE);

    // weight transpose+split conversions (independent; issue first)
    tconv_kernel<<<dim3(EE/32,   EE/32),   dim3(32,8)>>>(w_up,   gbup, EE,   EE);
    tconv_kernel<<<dim3(EE/32,   EE/32),   dim3(32,8)>>>(w_out,  gbout,EE,   EE);
    tconv_kernel<<<dim3(4*EE/32, EE/32),   dim3(32,8)>>>(w_mlp1, gbm1, EE,   4*EE);
    tconv_kernel<<<dim3(EE/32,   4*EE/32), dim3(32,8)>>>(w_mlp2, gbm2, 4*EE, EE);

    // 1) ln1 -> A split
    ln_split_kernel<<<BSZ, 256>>>(act, ln1g, ga2);

    // 2) new_m = (x @ w_up) * SCALE + I   -> stored in d_out act region (fp32)
    mgemm_kernel<1><<<dim3(EE/128, BSZ/128), 256>>>(
        ga2, gbup, out_act, EE, EE, nullptr, nullptr, 0);

    // 3) scan (reads newm from d_out) -> A split for gemm2 + states output
    scan_kernel<<<BB*HH, 256>>>(out_act, lstate, w_down, ga2, out_states, write_states);

    // 4) act = activations + down @ w_out  (overwrites consumed newm in d_out)
    mgemm_kernel<2><<<dim3(EE/128, BSZ/128), 256>>>(
        ga2, gbout, out_act, EE, EE, act, nullptr, 0);

    // 5) ln2 -> A split
    ln_split_kernel<<<BSZ, 256>>>(out_act, ln2g, ga2);

    // 6) hidden = gelu(y @ w_mlp1) -> A split for gemm4 (overwrites g_a2b incl. dead w_up/w_out)
    mgemm_kernel<3><<<dim3(4*EE/128, BSZ/128), 256>>>(
        ga2, gbm1, nullptr, 4*EE, EE, nullptr, ga2b, 4*EE);

    // 7) act = act + hidden @ w_mlp2  (in-place residual on d_out)
    mgemm_kernel<2><<<dim3(EE/128, BSZ/128), 256>>>(
        ga2b, gbm2, out_act, EE, 4*EE, out_act, nullptr, 0);
}